// round 1
// baseline (speedup 1.0000x reference)
#include <cuda_runtime.h>
#include <cstdint>

#define NBATCH 8
#define NNODE 2048
#define BN_TOTAL (NBATCH * NNODE)   // 16384
#define HID 128
#define PROJD 256
#define KNN 16
#define NEDGE (BN_TOTAL * KNN)      // 262144

// ---------------- scratch (device globals; no allocation) ----------------
__device__ float g_h  [BN_TOTAL * HID];
__device__ float g_t  [BN_TOTAL * HID];
__device__ float g_a  [BN_TOTAL * HID];
__device__ float g_bp [BN_TOTAL * HID];
__device__ float g_hu [BN_TOTAL * HID];
__device__ float g_agg[BN_TOTAL * HID];
__device__ int   g_nbr[NEDGE];
__device__ int   g_indeg[BN_TOTAL];
__device__ int   g_off[BN_TOTAL + 1];
__device__ int   g_cursor[BN_TOTAL];
__device__ float g_invdeg[BN_TOTAL];
__device__ int   g_rev[NEDGE];

// ---------------- kNN: warp per node, packed u64 keys ----------------
// key = (bits(dist) << 11) | j  -> min-order == (dist asc, index asc), matching top_k tie-break.
__global__ void __launch_bounds__(256) knn_k(const float* __restrict__ pos,
                                             int* __restrict__ nbr)
{
    __shared__ unsigned long long mb[8][512];
    const int warp = threadIdx.x >> 5;
    const int lane = threadIdx.x & 31;
    const int ng = blockIdx.x;            // 0..2047 (8 nodes per block)
    const int batch = ng >> 8;            // 256 blocks per batch
    const int n = ((ng & 255) << 3) + warp;
    const float* pb = pos + (size_t)batch * NNODE * 3;

    const float xi = pb[n * 3 + 0];
    const float yi = pb[n * 3 + 1];
    const float zi = pb[n * 3 + 2];

    unsigned long long best[KNN];
#pragma unroll
    for (int c = 0; c < KNN; ++c) best[c] = ~0ull;

    for (int t = 0; t < NNODE / 32; ++t) {
        const int j = lane + (t << 5);
        float dx = fabsf(xi - pb[j * 3 + 0]); if (dx > 0.5f) dx = 1.0f - dx;
        float dy = fabsf(yi - pb[j * 3 + 1]); if (dy > 0.5f) dy = 1.0f - dy;
        float dz = fabsf(zi - pb[j * 3 + 2]); if (dz > 0.5f) dz = 1.0f - dz;
        // replicate reference arithmetic exactly (no fma contraction, IEEE sqrt)
        float d2 = __fadd_rn(__fadd_rn(__fmul_rn(dx, dx), __fmul_rn(dy, dy)), __fmul_rn(dz, dz));
        float dist = __fsqrt_rn(__fadd_rn(d2, 1e-12f));
        unsigned long long key = ((unsigned long long)__float_as_uint(dist) << 11) | (unsigned)j;
        if (j == n) key = ~0ull;
        if (key < best[KNN - 1]) {
#pragma unroll
            for (int c = 0; c < KNN; ++c) {
                unsigned long long lo = best[c] < key ? best[c] : key;
                unsigned long long hi = best[c] < key ? key : best[c];
                best[c] = lo; key = hi;
            }
        }
    }
    // dump to smem (lane-interleaved: slot c -> mb[warp][c*32+lane], conflict-free)
#pragma unroll
    for (int c = 0; c < KNN; ++c) mb[warp][c * 32 + lane] = best[c];
    __syncwarp();

    int my_res = 0;
    for (int r = 0; r < KNN; ++r) {
        unsigned long long lmin = ~0ull; int ls = 0;
#pragma unroll
        for (int c = 0; c < KNN; ++c) {
            unsigned long long v = mb[warp][c * 32 + lane];
            if (v < lmin) { lmin = v; ls = c; }
        }
        unsigned long long g = lmin;
#pragma unroll
        for (int o = 16; o; o >>= 1) {
            unsigned long long v = __shfl_xor_sync(0xffffffffu, g, o);
            g = v < g ? v : g;
        }
        if (lmin == g) mb[warp][ls * 32 + lane] = ~0ull;   // keys unique -> exactly one lane
        if (lane == r) my_res = (int)(g & 2047ull);
        __syncwarp();
    }
    if (lane < KNN)
        nbr[((size_t)batch * NNODE + n) * KNN + lane] = batch * NNODE + my_res;
}

// ---------------- reverse-CSR build ----------------
__global__ void count_k(const int* __restrict__ nbr, int* __restrict__ indeg)
{
    int e = blockIdx.x * 256 + threadIdx.x;
    atomicAdd(&indeg[nbr[e]], 1);
}

__global__ void __launch_bounds__(1024) scan_k(const int* __restrict__ indeg,
                                               int* __restrict__ off,
                                               int* __restrict__ cursor,
                                               float* __restrict__ invdeg)
{
    __shared__ int s[1024];
    __shared__ int carry_s;
    const int tid = threadIdx.x;
    if (tid == 0) { carry_s = 0; off[0] = 0; }
    __syncthreads();
    for (int ch = 0; ch < BN_TOTAL / 1024; ++ch) {
        const int i = ch * 1024 + tid;
        const int v = indeg[i];
        int x = v;
        s[tid] = x;
        __syncthreads();
        for (int d = 1; d < 1024; d <<= 1) {
            int y = (tid >= d) ? s[tid - d] : 0;
            __syncthreads();
            x += y; s[tid] = x;
            __syncthreads();
        }
        const int incl = x + carry_s;
        off[i + 1] = incl;
        cursor[i] = incl - v;
        float fd = (float)v;
        invdeg[i] = 1.0f / (fd > 1.0f ? fd : 1.0f);
        __syncthreads();
        if (tid == 1023) carry_s = incl;
        __syncthreads();
    }
}

__global__ void fill_k(const int* __restrict__ nbr, int* __restrict__ cursor,
                       int* __restrict__ rev)
{
    int e = blockIdx.x * 256 + threadIdx.x;
    int j = nbr[e];
    int p = atomicAdd(&cursor[j], 1);
    rev[p] = e >> 4;                 // src node (global id)
}

// ---------------- encoder layer 0 (K=5) ----------------
__global__ void enc0_k(const float* __restrict__ x, const float* __restrict__ w,
                       const float* __restrict__ b, float* __restrict__ out)
{
    int g = blockIdx.x * 256 + threadIdx.x;        // < 16384*128
    int m = g >> 7, n = g & 127;
    const float* xr = x + m * 5;
    float s = b[n];
#pragma unroll
    for (int d = 0; d < 5; ++d) s += xr[d] * w[d * HID + n];
    out[g] = fmaxf(s, 0.0f);
}

// ---------------- generic GEMM: C = epilogue(A[MxK] @ W[KxN]) ----------------
// MODE 0: C = acc
// MODE 1: C = relu(acc + bias)
// MODE 2: C = acc + bias
// MODE 3: C = C + relu(acc + extra + bias)   (residual update, in-place on C)
template <int MODE>
__global__ void __launch_bounds__(256) gemm_k(const float* __restrict__ A,
                                              const float* __restrict__ W,
                                              const float* __restrict__ bias,
                                              const float* __restrict__ extra,
                                              float* __restrict__ C,
                                              int M, int N, int K)
{
    constexpr int BM = 128, BN = 64, BK = 16;
    __shared__ __align__(16) float As[BK][BM + 4];
    __shared__ __align__(16) float Ws[BK][BN];

    const int t = threadIdx.x;
    const int tx = t & 15;        // col group (4 cols)
    const int ty = t >> 4;        // row group (8 rows)
    const float* Ab = A + (size_t)blockIdx.y * BM * K;
    const float* Wb = W + blockIdx.x * BN;

    float acc[8][4];
#pragma unroll
    for (int i = 0; i < 8; ++i)
#pragma unroll
        for (int j = 0; j < 4; ++j) acc[i][j] = 0.0f;

    const int ar0 = t >> 2;            // 0..63
    const int ak0 = (t & 3) * 4;       // 0,4,8,12
    const int wr = t >> 4;             // 0..15
    const int wc = (t & 15) * 4;       // 0..60

    for (int k0 = 0; k0 < K; k0 += BK) {
        float4 a0 = *(const float4*)(Ab + (size_t)ar0 * K + k0 + ak0);
        float4 a1 = *(const float4*)(Ab + (size_t)(ar0 + 64) * K + k0 + ak0);
        float4 wv = *(const float4*)(Wb + (size_t)(k0 + wr) * N + wc);
        __syncthreads();
        As[ak0 + 0][ar0] = a0.x; As[ak0 + 1][ar0] = a0.y;
        As[ak0 + 2][ar0] = a0.z; As[ak0 + 3][ar0] = a0.w;
        As[ak0 + 0][ar0 + 64] = a1.x; As[ak0 + 1][ar0 + 64] = a1.y;
        As[ak0 + 2][ar0 + 64] = a1.z; As[ak0 + 3][ar0 + 64] = a1.w;
        *(float4*)&Ws[wr][wc] = wv;
        __syncthreads();
#pragma unroll
        for (int kk = 0; kk < BK; ++kk) {
            float4 aA = *(const float4*)&As[kk][ty * 8];
            float4 aB = *(const float4*)&As[kk][ty * 8 + 4];
            float4 bv = *(const float4*)&Ws[kk][tx * 4];
            float av[8] = {aA.x, aA.y, aA.z, aA.w, aB.x, aB.y, aB.z, aB.w};
#pragma unroll
            for (int i = 0; i < 8; ++i) {
                acc[i][0] += av[i] * bv.x;
                acc[i][1] += av[i] * bv.y;
                acc[i][2] += av[i] * bv.z;
                acc[i][3] += av[i] * bv.w;
            }
        }
    }

    const int row0 = blockIdx.y * BM + ty * 8;
    const int col = blockIdx.x * BN + tx * 4;
    float4 bv = make_float4(0.f, 0.f, 0.f, 0.f);
    if (MODE != 0) bv = *(const float4*)(bias + col);

#pragma unroll
    for (int i = 0; i < 8; ++i) {
        size_t o = (size_t)(row0 + i) * N + col;
        float4 r = make_float4(acc[i][0], acc[i][1], acc[i][2], acc[i][3]);
        if (MODE == 1) {
            r.x = fmaxf(r.x + bv.x, 0.f); r.y = fmaxf(r.y + bv.y, 0.f);
            r.z = fmaxf(r.z + bv.z, 0.f); r.w = fmaxf(r.w + bv.w, 0.f);
        } else if (MODE == 2) {
            r.x += bv.x; r.y += bv.y; r.z += bv.z; r.w += bv.w;
        } else if (MODE == 3) {
            float4 ev = *(const float4*)(extra + o);
            float4 cv = *(const float4*)(C + o);
            r.x = cv.x + fmaxf(r.x + ev.x + bv.x, 0.f);
            r.y = cv.y + fmaxf(r.y + ev.y + bv.y, 0.f);
            r.z = cv.z + fmaxf(r.z + ev.z + bv.z, 0.f);
            r.w = cv.w + fmaxf(r.w + ev.w + bv.w, 0.f);
        }
        *(float4*)(C + o) = r;
    }
}

// ---------------- aggregation: agg[j] = invdeg[j] * sum_in relu(a[src]+bp[j]+bias) ----------------
__global__ void __launch_bounds__(256) agg_k(const float* __restrict__ a,
                                             const float* __restrict__ bp,
                                             const float* __restrict__ msg_b,
                                             const int* __restrict__ off,
                                             const int* __restrict__ rev,
                                             const float* __restrict__ invdeg,
                                             float* __restrict__ agg)
{
    const int j = blockIdx.x * 8 + (threadIdx.x >> 5);
    const int lane = threadIdx.x & 31;
    const int c = lane * 4;

    float4 bpj = *(const float4*)&bp[(size_t)j * HID + c];
    float4 bb = *(const float4*)&msg_b[c];
    bpj.x += bb.x; bpj.y += bb.y; bpj.z += bb.z; bpj.w += bb.w;

    float4 acc = make_float4(0.f, 0.f, 0.f, 0.f);
    const int e1 = off[j + 1];
    for (int e = off[j]; e < e1; ++e) {
        int s = rev[e];
        float4 av = *(const float4*)&a[(size_t)s * HID + c];
        acc.x += fmaxf(av.x + bpj.x, 0.f);
        acc.y += fmaxf(av.y + bpj.y, 0.f);
        acc.z += fmaxf(av.z + bpj.z, 0.f);
        acc.w += fmaxf(av.w + bpj.w, 0.f);
    }
    const float w = invdeg[j];
    acc.x *= w; acc.y *= w; acc.z *= w; acc.w *= w;
    *(float4*)&agg[(size_t)j * HID + c] = acc;
}

// ---------------- host launch ----------------
extern "C" void kernel_launch(void* const* d_in, const int* in_sizes, int n_in,
                              void* d_out, int out_size)
{
    const float* x   = (const float*)d_in[0];
    const float* pos = (const float*)d_in[1];
    // "k" may or may not be passed as a device scalar; detect via size.
    const int wofs = (n_in >= 15 && in_sizes[2] == 1) ? 3 : 2;
    const float* enc_w0  = (const float*)d_in[wofs + 0];
    const float* enc_b0  = (const float*)d_in[wofs + 1];
    const float* enc_w1  = (const float*)d_in[wofs + 2];
    const float* enc_b1  = (const float*)d_in[wofs + 3];
    const float* msg_w   = (const float*)d_in[wofs + 4];
    const float* msg_b   = (const float*)d_in[wofs + 5];
    const float* upd_w   = (const float*)d_in[wofs + 6];
    const float* upd_b   = (const float*)d_in[wofs + 7];
    const float* proj_w0 = (const float*)d_in[wofs + 8];
    const float* proj_b0 = (const float*)d_in[wofs + 9];
    const float* proj_w1 = (const float*)d_in[wofs + 10];
    const float* proj_b1 = (const float*)d_in[wofs + 11];
    float* out = (float*)d_out;

    void *vh, *vt, *va, *vbp, *vhu, *vagg, *vnbr, *vdeg, *voff, *vcur, *vinv, *vrev;
    cudaGetSymbolAddress(&vh, g_h);     cudaGetSymbolAddress(&vt, g_t);
    cudaGetSymbolAddress(&va, g_a);     cudaGetSymbolAddress(&vbp, g_bp);
    cudaGetSymbolAddress(&vhu, g_hu);   cudaGetSymbolAddress(&vagg, g_agg);
    cudaGetSymbolAddress(&vnbr, g_nbr); cudaGetSymbolAddress(&vdeg, g_indeg);
    cudaGetSymbolAddress(&voff, g_off); cudaGetSymbolAddress(&vcur, g_cursor);
    cudaGetSymbolAddress(&vinv, g_invdeg); cudaGetSymbolAddress(&vrev, g_rev);
    float* h = (float*)vh;   float* tbuf = (float*)vt;
    float* a = (float*)va;   float* bp = (float*)vbp;
    float* hu = (float*)vhu; float* agg = (float*)vagg;
    int* nbr = (int*)vnbr;   int* deg = (int*)vdeg;
    int* off = (int*)voff;   int* cur = (int*)vcur;
    float* inv = (float*)vinv; int* rev = (int*)vrev;

    // graph build
    knn_k<<<BN_TOTAL / 8, 256>>>(pos, nbr);
    cudaMemsetAsync(deg, 0, BN_TOTAL * sizeof(int), 0);
    count_k<<<NEDGE / 256, 256>>>(nbr, deg);
    scan_k<<<1, 1024>>>(deg, off, cur, inv);
    fill_k<<<NEDGE / 256, 256>>>(nbr, cur, rev);

    // encoder
    enc0_k<<<BN_TOTAL * HID / 256, 256>>>(x, enc_w0, enc_b0, tbuf);
    gemm_k<1><<<dim3(HID / 64, BN_TOTAL / 128), 256>>>(tbuf, enc_w1, enc_b1, nullptr, h,
                                                       BN_TOTAL, HID, HID);
    // message passing
    for (int i = 0; i < 3; ++i) {
        const float* mw = msg_w + (size_t)i * 2 * HID * HID;
        const float* uw = upd_w + (size_t)i * 2 * HID * HID;
        gemm_k<0><<<dim3(2, 128), 256>>>(h, mw, nullptr, nullptr, a, BN_TOTAL, HID, HID);
        gemm_k<0><<<dim3(2, 128), 256>>>(h, mw + HID * HID, nullptr, nullptr, bp, BN_TOTAL, HID, HID);
        gemm_k<0><<<dim3(2, 128), 256>>>(h, uw, nullptr, nullptr, hu, BN_TOTAL, HID, HID);
        agg_k<<<BN_TOTAL / 8, 256>>>(a, bp, msg_b + i * HID, off, rev, inv, agg);
        gemm_k<3><<<dim3(2, 128), 256>>>(agg, uw + HID * HID, upd_b + i * HID, hu, h,
                                         BN_TOTAL, HID, HID);
    }
    // projection head
    gemm_k<1><<<dim3(2, 128), 256>>>(h, proj_w0, proj_b0, nullptr, tbuf, BN_TOTAL, HID, HID);
    gemm_k<2><<<dim3(PROJD / 64, 128), 256>>>(tbuf, proj_w1, proj_b1, nullptr, out,
                                              BN_TOTAL, PROJD, HID);
    // second output: h
    cudaMemcpyAsync(out + (size_t)BN_TOTAL * PROJD, h,
                    (size_t)BN_TOTAL * HID * sizeof(float),
                    cudaMemcpyDeviceToDevice, 0);
}

// round 3
// speedup vs baseline: 1.0425x; 1.0425x over previous
#include <cuda_runtime.h>
#include <cstdint>

#define NBATCH 8
#define NNODE 2048
#define BN_TOTAL (NBATCH * NNODE)   // 16384
#define HID 128
#define PROJD 256
#define KNN 16
#define NEDGE (BN_TOTAL * KNN)      // 262144

// ---------------- scratch (device globals; no allocation) ----------------
__device__ float g_h  [BN_TOTAL * HID];
__device__ float g_t  [BN_TOTAL * HID];
__device__ float g_a  [BN_TOTAL * HID];
__device__ float g_bp [BN_TOTAL * HID];
__device__ float g_hu [BN_TOTAL * HID];
__device__ float g_agg[BN_TOTAL * HID];
__device__ int   g_nbr[NEDGE];
__device__ int   g_indeg[BN_TOTAL];
__device__ int   g_off[BN_TOTAL + 1];
__device__ int   g_cursor[BN_TOTAL];
__device__ float g_invdeg[BN_TOTAL];
__device__ int   g_rev[NEDGE];

// ---------------- kNN: warp per node, packed u64 keys; fused in-degree count ----------------
__global__ void __launch_bounds__(256) knn_k(const float* __restrict__ pos,
                                             int* __restrict__ nbr,
                                             int* __restrict__ indeg)
{
    __shared__ unsigned long long mb[8][512];
    const int warp = threadIdx.x >> 5;
    const int lane = threadIdx.x & 31;
    const int ng = blockIdx.x;            // 0..2047 (8 nodes per block)
    const int batch = ng >> 8;
    const int n = ((ng & 255) << 3) + warp;
    const float* pb = pos + (size_t)batch * NNODE * 3;

    const float xi = pb[n * 3 + 0];
    const float yi = pb[n * 3 + 1];
    const float zi = pb[n * 3 + 2];

    unsigned long long best[KNN];
#pragma unroll
    for (int c = 0; c < KNN; ++c) best[c] = ~0ull;

    for (int t = 0; t < NNODE / 32; ++t) {
        const int j = lane + (t << 5);
        float dx = fabsf(xi - pb[j * 3 + 0]); if (dx > 0.5f) dx = 1.0f - dx;
        float dy = fabsf(yi - pb[j * 3 + 1]); if (dy > 0.5f) dy = 1.0f - dy;
        float dz = fabsf(zi - pb[j * 3 + 2]); if (dz > 0.5f) dz = 1.0f - dz;
        // replicate reference arithmetic exactly (no fma contraction, IEEE sqrt)
        float d2 = __fadd_rn(__fadd_rn(__fmul_rn(dx, dx), __fmul_rn(dy, dy)), __fmul_rn(dz, dz));
        float dist = __fsqrt_rn(__fadd_rn(d2, 1e-12f));
        unsigned long long key = ((unsigned long long)__float_as_uint(dist) << 11) | (unsigned)j;
        if (j == n) key = ~0ull;
        if (key < best[KNN - 1]) {
#pragma unroll
            for (int c = 0; c < KNN; ++c) {
                unsigned long long lo = best[c] < key ? best[c] : key;
                unsigned long long hi = best[c] < key ? key : best[c];
                best[c] = lo; key = hi;
            }
        }
    }
#pragma unroll
    for (int c = 0; c < KNN; ++c) mb[warp][c * 32 + lane] = best[c];
    __syncwarp();

    int my_res = 0;
    for (int r = 0; r < KNN; ++r) {
        unsigned long long lmin = ~0ull; int ls = 0;
#pragma unroll
        for (int c = 0; c < KNN; ++c) {
            unsigned long long v = mb[warp][c * 32 + lane];
            if (v < lmin) { lmin = v; ls = c; }
        }
        unsigned long long g = lmin;
#pragma unroll
        for (int o = 16; o; o >>= 1) {
            unsigned long long v = __shfl_xor_sync(0xffffffffu, g, o);
            g = v < g ? v : g;
        }
        if (lmin == g) mb[warp][ls * 32 + lane] = ~0ull;
        if (lane == r) my_res = (int)(g & 2047ull);
        __syncwarp();
    }
    if (lane < KNN) {
        const int dst = batch * NNODE + my_res;
        nbr[((size_t)batch * NNODE + n) * KNN + lane] = dst;
        atomicAdd(&indeg[dst], 1);
    }
}

// ---------------- reverse-CSR build ----------------
__global__ void __launch_bounds__(1024) scan_k(const int* __restrict__ indeg,
                                               int* __restrict__ off,
                                               int* __restrict__ cursor,
                                               float* __restrict__ invdeg)
{
    __shared__ int s[1024];
    __shared__ int carry_s;
    const int tid = threadIdx.x;
    if (tid == 0) { carry_s = 0; off[0] = 0; }
    __syncthreads();
    for (int ch = 0; ch < BN_TOTAL / 1024; ++ch) {
        const int i = ch * 1024 + tid;
        const int v = indeg[i];
        int x = v;
        s[tid] = x;
        __syncthreads();
        for (int d = 1; d < 1024; d <<= 1) {
            int y = (tid >= d) ? s[tid - d] : 0;
            __syncthreads();
            x += y; s[tid] = x;
            __syncthreads();
        }
        const int incl = x + carry_s;
        off[i + 1] = incl;
        cursor[i] = incl - v;
        float fd = (float)v;
        invdeg[i] = 1.0f / (fd > 1.0f ? fd : 1.0f);
        __syncthreads();
        if (tid == 1023) carry_s = incl;
        __syncthreads();
    }
}

__global__ void fill_k(const int* __restrict__ nbr, int* __restrict__ cursor,
                       int* __restrict__ rev)
{
    int e = blockIdx.x * 256 + threadIdx.x;
    int j = nbr[e];
    int p = atomicAdd(&cursor[j], 1);
    rev[p] = e >> 4;                 // src node (global id)
}

// ---------------- encoder layer 0 (K=5) ----------------
__global__ void enc0_k(const float* __restrict__ x, const float* __restrict__ w,
                       const float* __restrict__ b, float* __restrict__ out)
{
    int g = blockIdx.x * 256 + threadIdx.x;
    int m = g >> 7, n = g & 127;
    const float* xr = x + m * 5;
    float s = b[n];
#pragma unroll
    for (int d = 0; d < 5; ++d) s += xr[d] * w[d * HID + n];
    out[g] = fmaxf(s, 0.0f);
}

// ---------------- GEMM core: packed f32x2 FMAs ----------------
// Block tile: BM=128, BN=64, BK=16; thread tile 8x4 (4 cols = 2 f32x2 pairs).
__device__ __forceinline__ void gemm_compute(const float* __restrict__ Ab,
                                             const float* __restrict__ Wb,
                                             int N, int K,
                                             float (&As)[16][132],
                                             float (&Ws)[16][64],
                                             unsigned long long (&acc)[8][2])
{
    const int t = threadIdx.x;
    const int tx = t & 15;
    const int ty = t >> 4;
    const int ar0 = t >> 2;
    const int ak0 = (t & 3) * 4;
    const int wr = t >> 4;
    const int wc = (t & 15) * 4;

#pragma unroll
    for (int i = 0; i < 8; ++i) { acc[i][0] = 0ull; acc[i][1] = 0ull; }

    for (int k0 = 0; k0 < K; k0 += 16) {
        float4 a0 = *(const float4*)(Ab + (size_t)ar0 * K + k0 + ak0);
        float4 a1 = *(const float4*)(Ab + (size_t)(ar0 + 64) * K + k0 + ak0);
        float4 wv = *(const float4*)(Wb + (size_t)(k0 + wr) * N + wc);
        __syncthreads();
        As[ak0 + 0][ar0] = a0.x; As[ak0 + 1][ar0] = a0.y;
        As[ak0 + 2][ar0] = a0.z; As[ak0 + 3][ar0] = a0.w;
        As[ak0 + 0][ar0 + 64] = a1.x; As[ak0 + 1][ar0 + 64] = a1.y;
        As[ak0 + 2][ar0 + 64] = a1.z; As[ak0 + 3][ar0 + 64] = a1.w;
        *(float4*)&Ws[wr][wc] = wv;
        __syncthreads();
#pragma unroll
        for (int kk = 0; kk < 16; ++kk) {
            float4 aA = *(const float4*)&As[kk][ty * 8];
            float4 aB = *(const float4*)&As[kk][ty * 8 + 4];
            // float4 lands in an aligned register quad -> (x,y),(z,w) are valid 64-bit pairs
            ulonglong2 bv = *(const ulonglong2*)&Ws[kk][tx * 4];
            float av[8] = {aA.x, aA.y, aA.z, aA.w, aB.x, aB.y, aB.z, aB.w};
#pragma unroll
            for (int i = 0; i < 8; ++i) {
                unsigned long long ad;
                unsigned ai = __float_as_uint(av[i]);
                asm("mov.b64 %0, {%1, %1};" : "=l"(ad) : "r"(ai));
                asm("fma.rn.f32x2 %0, %1, %2, %0;" : "+l"(acc[i][0]) : "l"(ad), "l"(bv.x));
                asm("fma.rn.f32x2 %0, %1, %2, %0;" : "+l"(acc[i][1]) : "l"(ad), "l"(bv.y));
            }
        }
    }
}

__device__ __forceinline__ float2 unpack2(unsigned long long v)
{
    unsigned lo, hi;
    asm("mov.b64 {%0, %1}, %2;" : "=r"(lo), "=r"(hi) : "l"(v));
    return make_float2(__uint_as_float(lo), __uint_as_float(hi));
}

// MODE 0: C = acc
// MODE 1: C = relu(acc + bias)
// MODE 2: C = acc + bias
// MODE 3: C = C + relu(acc + extra + bias)
template <int MODE>
__device__ __forceinline__ void gemm_store(unsigned long long (&acc)[8][2],
                                           const float* __restrict__ bias,
                                           const float* __restrict__ extra,
                                           float* __restrict__ C,
                                           int N, int row0, int col)
{
    float4 bv = make_float4(0.f, 0.f, 0.f, 0.f);
    if (MODE != 0) bv = *(const float4*)(bias + col);
#pragma unroll
    for (int i = 0; i < 8; ++i) {
        size_t o = (size_t)(row0 + i) * N + col;
        float2 p0 = unpack2(acc[i][0]);
        float2 p1 = unpack2(acc[i][1]);
        float4 r = make_float4(p0.x, p0.y, p1.x, p1.y);
        if (MODE == 1) {
            r.x = fmaxf(r.x + bv.x, 0.f); r.y = fmaxf(r.y + bv.y, 0.f);
            r.z = fmaxf(r.z + bv.z, 0.f); r.w = fmaxf(r.w + bv.w, 0.f);
        } else if (MODE == 2) {
            r.x += bv.x; r.y += bv.y; r.z += bv.z; r.w += bv.w;
        } else if (MODE == 3) {
            float4 ev = *(const float4*)(extra + o);
            float4 cv = *(const float4*)(C + o);
            r.x = cv.x + fmaxf(r.x + ev.x + bv.x, 0.f);
            r.y = cv.y + fmaxf(r.y + ev.y + bv.y, 0.f);
            r.z = cv.z + fmaxf(r.z + ev.z + bv.z, 0.f);
            r.w = cv.w + fmaxf(r.w + ev.w + bv.w, 0.f);
        }
        *(float4*)(C + o) = r;
    }
}

template <int MODE>
__global__ void __launch_bounds__(256) gemm_k(const float* __restrict__ A,
                                              const float* __restrict__ W,
                                              const float* __restrict__ bias,
                                              const float* __restrict__ extra,
                                              float* __restrict__ C,
                                              int N, int K)
{
    __shared__ __align__(16) float As[16][132];
    __shared__ __align__(16) float Ws[16][64];
    unsigned long long acc[8][2];

    const float* Ab = A + (size_t)blockIdx.y * 128 * K;
    const float* Wb = W + blockIdx.x * 64;
    gemm_compute(Ab, Wb, N, K, As, Ws, acc);

    const int row0 = blockIdx.y * 128 + (threadIdx.x >> 4) * 8;
    const int col = blockIdx.x * 64 + (threadIdx.x & 15) * 4;
    gemm_store<MODE>(acc, bias, extra, C, N, row0, col);
}

// Fused pre-GEMMs for one MP round: a = h@mw_top, bp = h@mw_bot, hu = h@uw_top.
// grid = (6, 128): blockIdx.x>>1 selects {a,bp,hu}, &1 selects the 64-col half.
__global__ void __launch_bounds__(256) mp_pre_k(const float* __restrict__ h,
                                                const float* __restrict__ mw,
                                                const float* __restrict__ uw,
                                                float* __restrict__ a,
                                                float* __restrict__ bp,
                                                float* __restrict__ hu)
{
    __shared__ __align__(16) float As[16][132];
    __shared__ __align__(16) float Ws[16][64];
    unsigned long long acc[8][2];

    const int sel = blockIdx.x >> 1;
    const int cb = blockIdx.x & 1;
    const float* W = (sel == 0) ? mw : (sel == 1 ? mw + HID * HID : uw);
    float* C = (sel == 0) ? a : (sel == 1 ? bp : hu);

    const float* Ab = h + (size_t)blockIdx.y * 128 * HID;
    const float* Wb = W + cb * 64;
    gemm_compute(Ab, Wb, HID, HID, As, Ws, acc);

    const int row0 = blockIdx.y * 128 + (threadIdx.x >> 4) * 8;
    const int col = cb * 64 + (threadIdx.x & 15) * 4;
    gemm_store<0>(acc, nullptr, nullptr, C, HID, row0, col);
}

// ---------------- aggregation ----------------
__global__ void __launch_bounds__(256) agg_k(const float* __restrict__ a,
                                             const float* __restrict__ bp,
                                             const float* __restrict__ msg_b,
                                             const int* __restrict__ off,
                                             const int* __restrict__ rev,
                                             const float* __restrict__ invdeg,
                                             float* __restrict__ agg)
{
    const int j = blockIdx.x * 8 + (threadIdx.x >> 5);
    const int lane = threadIdx.x & 31;
    const int c = lane * 4;

    float4 bpj = *(const float4*)&bp[(size_t)j * HID + c];
    float4 bb = *(const float4*)&msg_b[c];
    bpj.x += bb.x; bpj.y += bb.y; bpj.z += bb.z; bpj.w += bb.w;

    float4 acc = make_float4(0.f, 0.f, 0.f, 0.f);
    const int e1 = off[j + 1];
    for (int e = off[j]; e < e1; ++e) {
        int s = rev[e];
        float4 av = *(const float4*)&a[(size_t)s * HID + c];
        acc.x += fmaxf(av.x + bpj.x, 0.f);
        acc.y += fmaxf(av.y + bpj.y, 0.f);
        acc.z += fmaxf(av.z + bpj.z, 0.f);
        acc.w += fmaxf(av.w + bpj.w, 0.f);
    }
    const float w = invdeg[j];
    acc.x *= w; acc.y *= w; acc.z *= w; acc.w *= w;
    *(float4*)&agg[(size_t)j * HID + c] = acc;
}

// ---------------- host launch ----------------
extern "C" void kernel_launch(void* const* d_in, const int* in_sizes, int n_in,
                              void* d_out, int out_size)
{
    const float* x   = (const float*)d_in[0];
    const float* pos = (const float*)d_in[1];
    const int wofs = (n_in >= 15 && in_sizes[2] == 1) ? 3 : 2;
    const float* enc_w0  = (const float*)d_in[wofs + 0];
    const float* enc_b0  = (const float*)d_in[wofs + 1];
    const float* enc_w1  = (const float*)d_in[wofs + 2];
    const float* enc_b1  = (const float*)d_in[wofs + 3];
    const float* msg_w   = (const float*)d_in[wofs + 4];
    const float* msg_b   = (const float*)d_in[wofs + 5];
    const float* upd_w   = (const float*)d_in[wofs + 6];
    const float* upd_b   = (const float*)d_in[wofs + 7];
    const float* proj_w0 = (const float*)d_in[wofs + 8];
    const float* proj_b0 = (const float*)d_in[wofs + 9];
    const float* proj_w1 = (const float*)d_in[wofs + 10];
    const float* proj_b1 = (const float*)d_in[wofs + 11];
    float* out = (float*)d_out;

    void *vh, *vt, *va, *vbp, *vhu, *vagg, *vnbr, *vdeg, *voff, *vcur, *vinv, *vrev;
    cudaGetSymbolAddress(&vh, g_h);     cudaGetSymbolAddress(&vt, g_t);
    cudaGetSymbolAddress(&va, g_a);     cudaGetSymbolAddress(&vbp, g_bp);
    cudaGetSymbolAddress(&vhu, g_hu);   cudaGetSymbolAddress(&vagg, g_agg);
    cudaGetSymbolAddress(&vnbr, g_nbr); cudaGetSymbolAddress(&vdeg, g_indeg);
    cudaGetSymbolAddress(&voff, g_off); cudaGetSymbolAddress(&vcur, g_cursor);
    cudaGetSymbolAddress(&vinv, g_invdeg); cudaGetSymbolAddress(&vrev, g_rev);
    float* h = (float*)vh;   float* tbuf = (float*)vt;
    float* a = (float*)va;   float* bp = (float*)vbp;
    float* hu = (float*)vhu; float* agg = (float*)vagg;
    int* nbr = (int*)vnbr;   int* deg = (int*)vdeg;
    int* off = (int*)voff;   int* cur = (int*)vcur;
    float* inv = (float*)vinv; int* rev = (int*)vrev;

    // graph build (degree count fused into knn)
    cudaMemsetAsync(deg, 0, BN_TOTAL * sizeof(int), 0);
    knn_k<<<BN_TOTAL / 8, 256>>>(pos, nbr, deg);
    scan_k<<<1, 1024>>>(deg, off, cur, inv);
    fill_k<<<NEDGE / 256, 256>>>(nbr, cur, rev);

    // encoder
    enc0_k<<<BN_TOTAL * HID / 256, 256>>>(x, enc_w0, enc_b0, tbuf);
    gemm_k<1><<<dim3(2, 128), 256>>>(tbuf, enc_w1, enc_b1, nullptr, h, HID, HID);

    // message passing
    for (int i = 0; i < 3; ++i) {
        const float* mw = msg_w + (size_t)i * 2 * HID * HID;
        const float* uw = upd_w + (size_t)i * 2 * HID * HID;
        mp_pre_k<<<dim3(6, 128), 256>>>(h, mw, uw, a, bp, hu);
        agg_k<<<BN_TOTAL / 8, 256>>>(a, bp, msg_b + i * HID, off, rev, inv, agg);
        gemm_k<3><<<dim3(2, 128), 256>>>(agg, uw + HID * HID, upd_b + i * HID, hu, h, HID, HID);
    }

    // projection head
    gemm_k<1><<<dim3(2, 128), 256>>>(h, proj_w0, proj_b0, nullptr, tbuf, HID, HID);
    gemm_k<2><<<dim3(PROJD / 64, 128), 256>>>(tbuf, proj_w1, proj_b1, nullptr, out, PROJD, HID);

    // second output: h
    cudaMemcpyAsync(out + (size_t)BN_TOTAL * PROJD, h,
                    (size_t)BN_TOTAL * HID * sizeof(float),
                    cudaMemcpyDeviceToDevice, 0);
}